// round 7
// baseline (speedup 1.0000x reference)
#include <cuda_runtime.h>
#include <math.h>
#include <stdint.h>

// Problem constants
#define Bsz 4
#define Sq  2048
#define Dm  1024
#define Hn  16
#define DHd 64
#define Mrows (Bsz * Sq)          // 8192
#define QKVCOLS (3 * Dm)          // 3072

// Scratch (allocation-free rule: __device__ globals)
__device__ float g_qkv[(size_t)Mrows * QKVCOLS];   // [8192, 3072] : Q|K|V
__device__ float g_attn[(size_t)Mrows * Dm];       // [8192, 1024] merged heads
__device__ float g_xc [(size_t)Mrows * Dm];        // x rounded to tf32
__device__ float g_wat[(size_t)QKVCOLS * Dm];      // w_attn^T [3072,1024] tf32
__device__ float g_wpt[(size_t)Dm * Dm];           // w_proj^T [1024,1024] tf32

// ---------------------------------------------------------------------------
// helpers
// ---------------------------------------------------------------------------
__device__ __forceinline__ float tf32r(float x) {
    uint32_t u;
    asm("cvt.rna.tf32.f32 %0, %1;" : "=r"(u) : "f"(x));
    return __uint_as_float(u);
}
__device__ __forceinline__ uint32_t tf32u(float x) {
    uint32_t u;
    asm("cvt.rna.tf32.f32 %0, %1;" : "=r"(u) : "f"(x));
    return u;
}
__device__ __forceinline__ uint32_t smem_u32(const void* p) {
    uint32_t a;
    asm("{ .reg .u64 t; cvta.to.shared.u64 t, %1; cvt.u32.u64 %0, t; }"
        : "=r"(a) : "l"(p));
    return a;
}

__device__ __forceinline__ void mma_tf32(float (&d)[4],
                                         const uint32_t (&a)[4],
                                         const uint32_t (&b)[2]) {
    asm volatile(
        "mma.sync.aligned.m16n8k8.row.col.f32.tf32.tf32.f32 "
        "{%0,%1,%2,%3}, {%4,%5,%6,%7}, {%8,%9}, {%0,%1,%2,%3};"
        : "+f"(d[0]), "+f"(d[1]), "+f"(d[2]), "+f"(d[3])
        : "r"(a[0]), "r"(a[1]), "r"(a[2]), "r"(a[3]), "r"(b[0]), "r"(b[1]));
}

#define LDSM4(r, addr) \
    asm volatile("ldmatrix.sync.aligned.m8n8.x4.shared.b16 {%0,%1,%2,%3}, [%4];" \
        : "=r"((r)[0]), "=r"((r)[1]), "=r"((r)[2]), "=r"((r)[3]) : "r"(addr))

#define CP_ASYNC16(dst, src) \
    asm volatile("cp.async.cg.shared.global [%0], [%1], 16;" :: "r"(dst), "l"(src))
#define CP_COMMIT()  asm volatile("cp.async.commit_group;")
#define CP_WAIT1()   asm volatile("cp.async.wait_group 1;")

// ---------------------------------------------------------------------------
// Elementwise round-to-tf32 (float4)
// ---------------------------------------------------------------------------
__global__ __launch_bounds__(256)
void cvt_tf32_kernel(const float* __restrict__ in, float* __restrict__ out) {
    int i = blockIdx.x * 256 + threadIdx.x;
    float4 v = ((const float4*)in)[i];
    v.x = tf32r(v.x); v.y = tf32r(v.y); v.z = tf32r(v.z); v.w = tf32r(v.w);
    ((float4*)out)[i] = v;
}

// ---------------------------------------------------------------------------
// Transpose + round-to-tf32: in[R][C] -> out[C][R]
// ---------------------------------------------------------------------------
__global__ __launch_bounds__(256)
void transpose_cvt_kernel(const float* __restrict__ in, float* __restrict__ out,
                          int R, int C) {
    __shared__ float t[32][33];
    const int c0 = blockIdx.x * 32, r0 = blockIdx.y * 32;
    const int tx = threadIdx.x, ty = threadIdx.y;   // 32 x 8
#pragma unroll
    for (int i = 0; i < 32; i += 8)
        t[ty + i][tx] = tf32r(in[(size_t)(r0 + ty + i) * C + c0 + tx]);
    __syncthreads();
#pragma unroll
    for (int i = 0; i < 32; i += 8)
        out[(size_t)(c0 + ty + i) * R + r0 + tx] = t[tx][ty + i];
}

// ---------------------------------------------------------------------------
// tf32 GEMM v3.1: C[M,N] = A[M,K] @ BT[N,K]^T + bias[N]
// CTA 128x128, 4 warps (2x2), warp tile 64x64.
// cp.async 3-stage pipeline (48KB smem), ldmatrix.x4 fragment loads.
// Smem row = 16 floats; quad q of row stored at q ^ ((row>>1)&3).
// FIX vs v3: stage s lives in buffer s%3; stage s+2 is written into
// buffer (buf+2)%3, not the just-freed buffer.
// ---------------------------------------------------------------------------
__global__ __launch_bounds__(128)
void gemm_mma_tf32(const float* __restrict__ A, const float* __restrict__ BT,
                   const float* __restrict__ bias, float* __restrict__ C,
                   int M, int N, int K)
{
    __shared__ __align__(16) float sA[3][128 * 16];   // 24KB
    __shared__ __align__(16) float sB[3][128 * 16];   // 24KB

    const int tid  = threadIdx.x;
    const int wid  = tid >> 5;
    const int lane = tid & 31;
    const int gid  = lane >> 2;
    const int tig  = lane & 3;
    const int wm   = wid & 1;
    const int wn   = wid >> 1;
    const int m0   = blockIdx.y * 128;
    const int n0   = blockIdx.x * 128;

    const uint32_t sAaddr = smem_u32(sA);
    const uint32_t sBaddr = smem_u32(sB);

    // --- staging descriptors: thread covers rows (tid>>2)+32i, quad tid&3 ---
    const int srow = tid >> 2;
    const int sq   = tid & 3;
    const uint32_t slotB = (uint32_t)(srow * 16 + ((sq ^ ((srow >> 1) & 3)) << 2)) * 4u;
    const float* aP = A  + (size_t)(m0 + srow) * K + sq * 4;
    const float* bP = BT + (size_t)(n0 + srow) * K + sq * 4;
    const size_t rstep = (size_t)32 * K;

    // --- ldmatrix per-lane address components ---
    const int lrow = lane & 15;            // row within 16-row block
    const int kh   = (lane >> 4) & 1;      // k-half select
    uint32_t aoff[4], boff[4];
    int xa[4], xb[4];
#pragma unroll
    for (int i = 0; i < 4; ++i) {
        int ra = wm * 64 + i * 16 + lrow;
        int rb = wn * 64 + i * 16 + lrow;
        aoff[i] = (uint32_t)ra * 64u;   // bytes (16 floats/row)
        boff[i] = (uint32_t)rb * 64u;
        xa[i] = (ra >> 1) & 3;
        xb[i] = (rb >> 1) & 3;
    }

    float acc[4][8][4];
#pragma unroll
    for (int mt = 0; mt < 4; ++mt)
#pragma unroll
        for (int nt = 0; nt < 8; ++nt)
#pragma unroll
            for (int e = 0; e < 4; ++e) acc[mt][nt][e] = 0.f;

    const int nst = K / 16;

    // --- prologue: stages 0,1 in flight (stage s -> buffer s%3) ---
#pragma unroll
    for (int s = 0; s < 2; ++s) {
        const uint32_t da = sAaddr + s * 8192u + slotB;
        const uint32_t db = sBaddr + s * 8192u + slotB;
        const int ko = s * 16;
#pragma unroll
        for (int i = 0; i < 4; ++i) {
            CP_ASYNC16(da + i * 2048u, aP + i * rstep + ko);
            CP_ASYNC16(db + i * 2048u, bP + i * rstep + ko);
        }
        CP_COMMIT();
    }

    int buf = 0;
    for (int s = 0; s < nst; ++s) {
        CP_WAIT1();
        __syncthreads();

        const uint32_t aB = sAaddr + buf * 8192u;
        const uint32_t bB = sBaddr + buf * 8192u;

#pragma unroll
        for (int kt = 0; kt < 2; ++kt) {
            const int kq = kt * 2 + kh;
            uint32_t af[4][4], bm[4][4];
#pragma unroll
            for (int mt = 0; mt < 4; ++mt)
                LDSM4(af[mt], aB + aoff[mt] + (uint32_t)((kq ^ xa[mt]) << 4));
#pragma unroll
            for (int p = 0; p < 4; ++p)
                LDSM4(bm[p], bB + boff[p] + (uint32_t)((kq ^ xb[p]) << 4));
#pragma unroll
            for (int nt = 0; nt < 8; ++nt) {
                uint32_t bfr[2] = { bm[nt >> 1][nt & 1], bm[nt >> 1][2 + (nt & 1)] };
#pragma unroll
                for (int mt = 0; mt < 4; ++mt)
                    mma_tf32(acc[mt][nt], af[mt], bfr);
            }
        }

        __syncthreads();

        // issue stage s+2 into buffer (s+2)%3; commit ALWAYS (empty tail
        // groups keep the wait_group 1 accounting sound)
        if (s + 2 < nst) {
            const int wb = (buf + 2) % 3;    // == (s+2) % 3
            const uint32_t da = sAaddr + wb * 8192u + slotB;
            const uint32_t db = sBaddr + wb * 8192u + slotB;
            const int ko = (s + 2) * 16;
#pragma unroll
            for (int i = 0; i < 4; ++i) {
                CP_ASYNC16(da + i * 2048u, aP + i * rstep + ko);
                CP_ASYNC16(db + i * 2048u, bP + i * rstep + ko);
            }
        }
        CP_COMMIT();

        buf = (buf == 2) ? 0 : buf + 1;
    }

    // Epilogue: + bias, store
#pragma unroll
    for (int mt = 0; mt < 4; ++mt) {
        const int r = m0 + wm * 64 + mt * 16 + gid;
#pragma unroll
        for (int nt = 0; nt < 8; ++nt) {
            const int c = n0 + wn * 64 + nt * 8 + tig * 2;
            float b0 = bias[c], b1 = bias[c + 1];
            float2 v0 = make_float2(acc[mt][nt][0] + b0, acc[mt][nt][1] + b1);
            float2 v1 = make_float2(acc[mt][nt][2] + b0, acc[mt][nt][3] + b1);
            *(float2*)&C[(size_t)r * N + c] = v0;
            *(float2*)&C[(size_t)(r + 8) * N + c] = v1;
        }
    }
}

// ---------------------------------------------------------------------------
// Flash attention with mma.sync tf32 (unchanged from round 5).
// ---------------------------------------------------------------------------
__global__ __launch_bounds__(128, 2)
void attn_mma_kernel(const float* __restrict__ qkv, float* __restrict__ out)
{
    __shared__ __align__(16) float sm[64 * 68 + 64 * 72];  // 35840 B
    float* sK  = sm;             // [64 key][68]
    float* sVt = sm + 64 * 68;   // [64 dh][72]

    const int tid  = threadIdx.x;
    const int wid  = tid >> 5;
    const int lane = tid & 31;
    const int gid  = lane >> 2;
    const int tig  = lane & 3;
    const int h    = blockIdx.y;
    const int b    = blockIdx.z;
    const int qr0  = blockIdx.x * 128;

    const size_t rs = (size_t)QKVCOLS;
    const float* qbase = qkv + (size_t)(b * Sq + qr0) * rs + h * DHd;

#pragma unroll
    for (int i = 0; i < 16; ++i) {
        int v = tid + i * 128;
        int row = v >> 4, c4 = v & 15;
        float4 q4 = *(const float4*)(qbase + (size_t)row * rs + c4 * 4);
        *(float4*)(sm + row * 68 + c4 * 4) = q4;
    }
    __syncthreads();

    uint32_t qa[2][8][4];
#pragma unroll
    for (int mt = 0; mt < 2; ++mt) {
        const int r0 = wid * 32 + mt * 16 + gid;
#pragma unroll
        for (int kt = 0; kt < 8; ++kt) {
            const int c = kt * 8 + tig;
            qa[mt][kt][0] = tf32u(sm[r0 * 68 + c] * 0.125f);
            qa[mt][kt][1] = tf32u(sm[(r0 + 8) * 68 + c] * 0.125f);
            qa[mt][kt][2] = tf32u(sm[r0 * 68 + c + 4] * 0.125f);
            qa[mt][kt][3] = tf32u(sm[(r0 + 8) * 68 + c + 4] * 0.125f);
        }
    }
    __syncthreads();

    float oacc[2][8][4];
#pragma unroll
    for (int mt = 0; mt < 2; ++mt)
#pragma unroll
        for (int dt = 0; dt < 8; ++dt)
#pragma unroll
            for (int e = 0; e < 4; ++e) oacc[mt][dt][e] = 0.f;
    float mrow[2][2] = {{-1e30f, -1e30f}, {-1e30f, -1e30f}};
    float lrow[2][2] = {{0.f, 0.f}, {0.f, 0.f}};

    const int ntiles = qr0 / 64 + 2;
    const int rv = tid & 63;
    const int ch = (tid >> 6) * 8;

    for (int t = 0; t < ntiles; ++t) {
        const int j0 = t * 64;
        const float* kb = qkv + (size_t)(b * Sq + j0) * rs + Dm + h * DHd;
        const float* vb = kb + Dm;

#pragma unroll
        for (int i = 0; i < 8; ++i) {
            int v = tid + i * 128;
            int row = v >> 4, c4 = v & 15;
            float4 k4 = *(const float4*)(kb + (size_t)row * rs + c4 * 4);
            k4.x = tf32r(k4.x); k4.y = tf32r(k4.y);
            k4.z = tf32r(k4.z); k4.w = tf32r(k4.w);
            *(float4*)(sK + row * 68 + c4 * 4) = k4;
        }
        const float* vrow = vb + (size_t)rv * rs + ch * 4;
#pragma unroll
        for (int j = 0; j < 8; ++j) {
            const int c4 = ch + j;
            float4 v4 = *(const float4*)(vrow + j * 4);
            sVt[(c4 * 4 + 0) * 72 + rv] = tf32r(v4.x);
            sVt[(c4 * 4 + 1) * 72 + rv] = tf32r(v4.y);
            sVt[(c4 * 4 + 2) * 72 + rv] = tf32r(v4.z);
            sVt[(c4 * 4 + 3) * 72 + rv] = tf32r(v4.w);
        }
        __syncthreads();

        float sacc[2][8][4];
#pragma unroll
        for (int mt = 0; mt < 2; ++mt)
#pragma unroll
            for (int nt = 0; nt < 8; ++nt)
#pragma unroll
                for (int e = 0; e < 4; ++e) sacc[mt][nt][e] = 0.f;

#pragma unroll
        for (int nt = 0; nt < 8; ++nt) {
            const int krow = (nt * 8 + gid) * 68;
#pragma unroll
            for (int kt = 0; kt < 8; ++kt) {
                uint32_t kf[2];
                kf[0] = __float_as_uint(sK[krow + kt * 8 + tig]);
                kf[1] = __float_as_uint(sK[krow + kt * 8 + tig + 4]);
                mma_tf32(sacc[0][nt], qa[0][kt], kf);
                mma_tf32(sacc[1][nt], qa[1][kt], kf);
            }
        }

        if (j0 + 63 > qr0) {
#pragma unroll
            for (int mt = 0; mt < 2; ++mt) {
                const int r0 = qr0 + wid * 32 + mt * 16 + gid;
#pragma unroll
                for (int nt = 0; nt < 8; ++nt) {
                    const int c = j0 + nt * 8 + 2 * tig;
                    if (c > r0)         sacc[mt][nt][0] = -1e30f;
                    if (c + 1 > r0)     sacc[mt][nt][1] = -1e30f;
                    if (c > r0 + 8)     sacc[mt][nt][2] = -1e30f;
                    if (c + 1 > r0 + 8) sacc[mt][nt][3] = -1e30f;
                }
            }
        }

#pragma unroll
        for (int mt = 0; mt < 2; ++mt) {
#pragma unroll
            for (int hf = 0; hf < 2; ++hf) {
                float mx = mrow[mt][hf];
#pragma unroll
                for (int nt = 0; nt < 8; ++nt)
                    mx = fmaxf(mx, fmaxf(sacc[mt][nt][hf * 2],
                                         sacc[mt][nt][hf * 2 + 1]));
                mx = fmaxf(mx, __shfl_xor_sync(0xffffffffu, mx, 1));
                mx = fmaxf(mx, __shfl_xor_sync(0xffffffffu, mx, 2));
                const float alpha = __expf(mrow[mt][hf] - mx);
                mrow[mt][hf] = mx;
                float lsum = lrow[mt][hf] * alpha;
#pragma unroll
                for (int nt = 0; nt < 8; ++nt) {
                    float p0 = __expf(sacc[mt][nt][hf * 2] - mx);
                    float p1 = __expf(sacc[mt][nt][hf * 2 + 1] - mx);
                    sacc[mt][nt][hf * 2] = p0;
                    sacc[mt][nt][hf * 2 + 1] = p1;
                    lsum += p0 + p1;
                }
                lrow[mt][hf] = lsum;
#pragma unroll
                for (int dt = 0; dt < 8; ++dt) {
                    oacc[mt][dt][hf * 2]     *= alpha;
                    oacc[mt][dt][hf * 2 + 1] *= alpha;
                }
            }
        }

#pragma unroll
        for (int dt = 0; dt < 8; ++dt) {
            const int vrow2 = (dt * 8 + gid) * 72;
#pragma unroll
            for (int kt = 0; kt < 8; ++kt) {
                float2 vv = *(const float2*)(sVt + vrow2 + kt * 8 + 2 * tig);
                uint32_t vf[2] = {__float_as_uint(vv.x), __float_as_uint(vv.y)};
#pragma unroll
                for (int mt = 0; mt < 2; ++mt) {
                    uint32_t pf[4] = {__float_as_uint(sacc[mt][kt][0]),
                                      __float_as_uint(sacc[mt][kt][2]),
                                      __float_as_uint(sacc[mt][kt][1]),
                                      __float_as_uint(sacc[mt][kt][3])};
                    mma_tf32(oacc[mt][dt], pf, vf);
                }
            }
        }
        __syncthreads();
    }

#pragma unroll
    for (int mt = 0; mt < 2; ++mt)
#pragma unroll
        for (int hf = 0; hf < 2; ++hf) {
            float l = lrow[mt][hf];
            l += __shfl_xor_sync(0xffffffffu, l, 1);
            l += __shfl_xor_sync(0xffffffffu, l, 2);
            lrow[mt][hf] = 1.f / l;
        }

    float* ob = out + (size_t)(b * Sq + qr0) * Dm + h * DHd;
#pragma unroll
    for (int mt = 0; mt < 2; ++mt) {
        const int r0 = wid * 32 + mt * 16 + gid;
#pragma unroll
        for (int dt = 0; dt < 8; ++dt) {
            const int c = dt * 8 + 2 * tig;
            float2 w0, w1;
            w0.x = tf32r(oacc[mt][dt][0] * lrow[mt][0]);
            w0.y = tf32r(oacc[mt][dt][1] * lrow[mt][0]);
            w1.x = tf32r(oacc[mt][dt][2] * lrow[mt][1]);
            w1.y = tf32r(oacc[mt][dt][3] * lrow[mt][1]);
            *(float2*)(ob + (size_t)r0 * Dm + c) = w0;
            *(float2*)(ob + (size_t)(r0 + 8) * Dm + c) = w1;
        }
    }
}

// ---------------------------------------------------------------------------
// Launch
// ---------------------------------------------------------------------------
extern "C" void kernel_launch(void* const* d_in, const int* in_sizes, int n_in,
                              void* d_out, int out_size)
{
    const float* x      = (const float*)d_in[0];  // [B,S,D]
    const float* w_attn = (const float*)d_in[1];  // [D,3D]
    const float* b_attn = (const float*)d_in[2];  // [3D]
    const float* w_proj = (const float*)d_in[3];  // [D,D]
    const float* b_proj = (const float*)d_in[4];  // [D]
    float* out = (float*)d_out;

    float *qkv, *attn, *xc, *wat, *wpt;
    cudaGetSymbolAddress((void**)&qkv,  g_qkv);
    cudaGetSymbolAddress((void**)&attn, g_attn);
    cudaGetSymbolAddress((void**)&xc,   g_xc);
    cudaGetSymbolAddress((void**)&wat,  g_wat);
    cudaGetSymbolAddress((void**)&wpt,  g_wpt);

    // 0) tf32 rounding / weight transposes
    cvt_tf32_kernel<<<(Mrows * Dm) / (4 * 256), 256>>>(x, xc);
    transpose_cvt_kernel<<<dim3(QKVCOLS / 32, Dm / 32), dim3(32, 8)>>>(
        w_attn, wat, Dm, QKVCOLS);
    transpose_cvt_kernel<<<dim3(Dm / 32, Dm / 32), dim3(32, 8)>>>(
        w_proj, wpt, Dm, Dm);

    // 1) QKV projection (mma.sync tf32 + ldmatrix + cp.async)
    gemm_mma_tf32<<<dim3(QKVCOLS / 128, Mrows / 128), 128>>>(
        xc, wat, b_attn, qkv, Mrows, QKVCOLS, Dm);

    // 2) Causal multi-head attention (mma.sync tf32 flash)
    attn_mma_kernel<<<dim3(Sq / 128, Hn, Bsz), 128>>>(qkv, attn);

    // 3) Output projection (mma.sync tf32 + ldmatrix + cp.async)
    gemm_mma_tf32<<<dim3(Dm / 128, Mrows / 128), 128>>>(
        attn, wpt, b_proj, out, Mrows, Dm, Dm);
}

// round 8
// speedup vs baseline: 1.0461x; 1.0461x over previous
#include <cuda_runtime.h>
#include <math.h>
#include <stdint.h>

// Problem constants
#define Bsz 4
#define Sq  2048
#define Dm  1024
#define Hn  16
#define DHd 64
#define Mrows (Bsz * Sq)          // 8192
#define QKVCOLS (3 * Dm)          // 3072

// Scratch (allocation-free rule: __device__ globals)
__device__ float g_qkv[(size_t)Mrows * QKVCOLS];   // [8192, 3072] : Q|K|V
__device__ float g_attn[(size_t)Mrows * Dm];       // [8192, 1024] merged heads
__device__ float g_xc [(size_t)Mrows * Dm];        // x rounded to tf32
__device__ float g_wat[(size_t)QKVCOLS * Dm];      // w_attn^T [3072,1024] tf32
__device__ float g_wpt[(size_t)Dm * Dm];           // w_proj^T [1024,1024] tf32

// ---------------------------------------------------------------------------
// helpers
// ---------------------------------------------------------------------------
__device__ __forceinline__ float tf32r(float x) {
    uint32_t u;
    asm("cvt.rna.tf32.f32 %0, %1;" : "=r"(u) : "f"(x));
    return __uint_as_float(u);
}
__device__ __forceinline__ uint32_t tf32u(float x) {
    uint32_t u;
    asm("cvt.rna.tf32.f32 %0, %1;" : "=r"(u) : "f"(x));
    return u;
}
__device__ __forceinline__ uint32_t smem_u32(const void* p) {
    uint32_t a;
    asm("{ .reg .u64 t; cvta.to.shared.u64 t, %1; cvt.u32.u64 %0, t; }"
        : "=r"(a) : "l"(p));
    return a;
}

__device__ __forceinline__ void mma_tf32(float (&d)[4],
                                         const uint32_t (&a)[4],
                                         const uint32_t (&b)[2]) {
    asm volatile(
        "mma.sync.aligned.m16n8k8.row.col.f32.tf32.tf32.f32 "
        "{%0,%1,%2,%3}, {%4,%5,%6,%7}, {%8,%9}, {%0,%1,%2,%3};"
        : "+f"(d[0]), "+f"(d[1]), "+f"(d[2]), "+f"(d[3])
        : "r"(a[0]), "r"(a[1]), "r"(a[2]), "r"(a[3]), "r"(b[0]), "r"(b[1]));
}

#define LDSM4(r, addr) \
    asm volatile("ldmatrix.sync.aligned.m8n8.x4.shared.b16 {%0,%1,%2,%3}, [%4];" \
        : "=r"((r)[0]), "=r"((r)[1]), "=r"((r)[2]), "=r"((r)[3]) : "r"(addr))

#define CP_ASYNC16(dst, src) \
    asm volatile("cp.async.cg.shared.global [%0], [%1], 16;" :: "r"(dst), "l"(src))
#define CP_COMMIT()  asm volatile("cp.async.commit_group;")
#define CP_WAIT1()   asm volatile("cp.async.wait_group 1;")

// ---------------------------------------------------------------------------
// Elementwise round-to-tf32 (float4)
// ---------------------------------------------------------------------------
__global__ __launch_bounds__(256)
void cvt_tf32_kernel(const float* __restrict__ in, float* __restrict__ out) {
    int i = blockIdx.x * 256 + threadIdx.x;
    float4 v = ((const float4*)in)[i];
    v.x = tf32r(v.x); v.y = tf32r(v.y); v.z = tf32r(v.z); v.w = tf32r(v.w);
    ((float4*)out)[i] = v;
}

// ---------------------------------------------------------------------------
// Transpose + round-to-tf32: in[R][C] -> out[C][R]
// ---------------------------------------------------------------------------
__global__ __launch_bounds__(256)
void transpose_cvt_kernel(const float* __restrict__ in, float* __restrict__ out,
                          int R, int C) {
    __shared__ float t[32][33];
    const int c0 = blockIdx.x * 32, r0 = blockIdx.y * 32;
    const int tx = threadIdx.x, ty = threadIdx.y;   // 32 x 8
#pragma unroll
    for (int i = 0; i < 32; i += 8)
        t[ty + i][tx] = tf32r(in[(size_t)(r0 + ty + i) * C + c0 + tx]);
    __syncthreads();
#pragma unroll
    for (int i = 0; i < 32; i += 8)
        out[(size_t)(c0 + ty + i) * R + r0 + tx] = t[tx][ty + i];
}

// ---------------------------------------------------------------------------
// tf32 GEMM v4: C[M,N] = A[M,K] @ BT[N,K]^T + bias[N]
// CTA 128x128, 8 warps (2m x 4n), warp tile 64x32. 256 threads, 2 CTA/SM.
// cp.async 3-stage pipeline (48KB smem), ldmatrix.x4 fragment loads,
// ONE __syncthreads per stage (write target (s+2)%3 == (s-1)%3, whose reads
// completed before this iteration's barrier).
// Smem row = 16 floats; quad q of row stored at q ^ ((row>>1)&3).
// ---------------------------------------------------------------------------
__global__ __launch_bounds__(256, 2)
void gemm_mma_tf32(const float* __restrict__ A, const float* __restrict__ BT,
                   const float* __restrict__ bias, float* __restrict__ C,
                   int M, int N, int K)
{
    __shared__ __align__(16) float sA[3][128 * 16];   // 24KB
    __shared__ __align__(16) float sB[3][128 * 16];   // 24KB

    const int tid  = threadIdx.x;
    const int wid  = tid >> 5;
    const int lane = tid & 31;
    const int gid  = lane >> 2;
    const int tig  = lane & 3;
    const int wm   = wid & 1;        // 0..1 -> 64 rows
    const int wn   = wid >> 1;       // 0..3 -> 32 cols
    const int m0   = blockIdx.y * 128;
    const int n0   = blockIdx.x * 128;

    const uint32_t sAaddr = smem_u32(sA);
    const uint32_t sBaddr = smem_u32(sB);

    // --- staging: thread covers rows (tid>>2) and (tid>>2)+64, quad tid&3 ---
    // xor key of row+64 equals that of row (64>>1 = 32 == 0 mod 4)
    const int srow = tid >> 2;       // 0..63
    const int sq   = tid & 3;
    const uint32_t slotB = (uint32_t)(srow * 16 + ((sq ^ ((srow >> 1) & 3)) << 2)) * 4u;
    const float* aP = A  + (size_t)(m0 + srow) * K + sq * 4;
    const float* bP = BT + (size_t)(n0 + srow) * K + sq * 4;
    const size_t rstep = (size_t)64 * K;

    // --- ldmatrix per-lane address components ---
    const int lrow = lane & 15;            // row within 16-row block
    const int kh   = (lane >> 4) & 1;      // k-half select
    uint32_t aoff[4], boff[2];
    int xa[4], xb[2];
#pragma unroll
    for (int i = 0; i < 4; ++i) {
        int ra = wm * 64 + i * 16 + lrow;
        aoff[i] = (uint32_t)ra * 64u;   // bytes (16 floats/row)
        xa[i] = (ra >> 1) & 3;
    }
#pragma unroll
    for (int i = 0; i < 2; ++i) {
        int rb = wn * 32 + i * 16 + lrow;
        boff[i] = (uint32_t)rb * 64u;
        xb[i] = (rb >> 1) & 3;
    }

    float acc[4][4][4];
#pragma unroll
    for (int mt = 0; mt < 4; ++mt)
#pragma unroll
        for (int nt = 0; nt < 4; ++nt)
#pragma unroll
            for (int e = 0; e < 4; ++e) acc[mt][nt][e] = 0.f;

    const int nst = K / 16;

    // --- prologue: stages 0,1 in flight (stage s -> buffer s%3) ---
#pragma unroll
    for (int s = 0; s < 2; ++s) {
        const uint32_t da = sAaddr + s * 8192u + slotB;
        const uint32_t db = sBaddr + s * 8192u + slotB;
        const int ko = s * 16;
#pragma unroll
        for (int i = 0; i < 2; ++i) {
            CP_ASYNC16(da + i * 4096u, aP + i * rstep + ko);
            CP_ASYNC16(db + i * 4096u, bP + i * rstep + ko);
        }
        CP_COMMIT();
    }

    int buf = 0;
    for (int s = 0; s < nst; ++s) {
        CP_WAIT1();
        __syncthreads();

        const uint32_t aB = sAaddr + buf * 8192u;
        const uint32_t bB = sBaddr + buf * 8192u;

        // issue stage s+2 into buffer (s+2)%3 (same as (s-1)%3 — its reads
        // finished before this iteration's barrier). Commit ALWAYS so the
        // wait_group 1 accounting stays sound at the tail.
        if (s + 2 < nst) {
            const int wb = (buf + 2) % 3;
            const uint32_t da = sAaddr + wb * 8192u + slotB;
            const uint32_t db = sBaddr + wb * 8192u + slotB;
            const int ko = (s + 2) * 16;
#pragma unroll
            for (int i = 0; i < 2; ++i) {
                CP_ASYNC16(da + i * 4096u, aP + i * rstep + ko);
                CP_ASYNC16(db + i * 4096u, bP + i * rstep + ko);
            }
        }
        CP_COMMIT();

#pragma unroll
        for (int kt = 0; kt < 2; ++kt) {
            const int kq = kt * 2 + kh;
            uint32_t af[4][4], bm[2][4];
#pragma unroll
            for (int mt = 0; mt < 4; ++mt)
                LDSM4(af[mt], aB + aoff[mt] + (uint32_t)((kq ^ xa[mt]) << 4));
#pragma unroll
            for (int p = 0; p < 2; ++p)
                LDSM4(bm[p], bB + boff[p] + (uint32_t)((kq ^ xb[p]) << 4));
#pragma unroll
            for (int nt = 0; nt < 4; ++nt) {
                uint32_t bfr[2] = { bm[nt >> 1][nt & 1], bm[nt >> 1][2 + (nt & 1)] };
#pragma unroll
                for (int mt = 0; mt < 4; ++mt)
                    mma_tf32(acc[mt][nt], af[mt], bfr);
            }
        }

        buf = (buf == 2) ? 0 : buf + 1;
    }

    // Epilogue: + bias, store
#pragma unroll
    for (int mt = 0; mt < 4; ++mt) {
        const int r = m0 + wm * 64 + mt * 16 + gid;
#pragma unroll
        for (int nt = 0; nt < 4; ++nt) {
            const int c = n0 + wn * 32 + nt * 8 + tig * 2;
            float b0 = bias[c], b1 = bias[c + 1];
            float2 v0 = make_float2(acc[mt][nt][0] + b0, acc[mt][nt][1] + b1);
            float2 v1 = make_float2(acc[mt][nt][2] + b0, acc[mt][nt][3] + b1);
            *(float2*)&C[(size_t)r * N + c] = v0;
            *(float2*)&C[(size_t)(r + 8) * N + c] = v1;
        }
    }
}

// ---------------------------------------------------------------------------
// Flash attention with mma.sync tf32 (unchanged from round 5).
// ---------------------------------------------------------------------------
__global__ __launch_bounds__(128, 2)
void attn_mma_kernel(const float* __restrict__ qkv, float* __restrict__ out)
{
    __shared__ __align__(16) float sm[64 * 68 + 64 * 72];  // 35840 B
    float* sK  = sm;             // [64 key][68]
    float* sVt = sm + 64 * 68;   // [64 dh][72]

    const int tid  = threadIdx.x;
    const int wid  = tid >> 5;
    const int lane = tid & 31;
    const int gid  = lane >> 2;
    const int tig  = lane & 3;
    const int h    = blockIdx.y;
    const int b    = blockIdx.z;
    const int qr0  = blockIdx.x * 128;

    const size_t rs = (size_t)QKVCOLS;
    const float* qbase = qkv + (size_t)(b * Sq + qr0) * rs + h * DHd;

#pragma unroll
    for (int i = 0; i < 16; ++i) {
        int v = tid + i * 128;
        int row = v >> 4, c4 = v & 15;
        float4 q4 = *(const float4*)(qbase + (size_t)row * rs + c4 * 4);
        *(float4*)(sm + row * 68 + c4 * 4) = q4;
    }
    __syncthreads();

    uint32_t qa[2][8][4];
#pragma unroll
    for (int mt = 0; mt < 2; ++mt) {
        const int r0 = wid * 32 + mt * 16 + gid;
#pragma unroll
        for (int kt = 0; kt < 8; ++kt) {
            const int c = kt * 8 + tig;
            qa[mt][kt][0] = tf32u(sm[r0 * 68 + c] * 0.125f);
            qa[mt][kt][1] = tf32u(sm[(r0 + 8) * 68 + c] * 0.125f);
            qa[mt][kt][2] = tf32u(sm[r0 * 68 + c + 4] * 0.125f);
            qa[mt][kt][3] = tf32u(sm[(r0 + 8) * 68 + c + 4] * 0.125f);
        }
    }
    __syncthreads();

    float oacc[2][8][4];
#pragma unroll
    for (int mt = 0; mt < 2; ++mt)
#pragma unroll
        for (int dt = 0; dt < 8; ++dt)
#pragma unroll
            for (int e = 0; e < 4; ++e) oacc[mt][dt][e] = 0.f;
    float mrow[2][2] = {{-1e30f, -1e30f}, {-1e30f, -1e30f}};
    float lrow[2][2] = {{0.f, 0.f}, {0.f, 0.f}};

    const int ntiles = qr0 / 64 + 2;
    const int rv = tid & 63;
    const int ch = (tid >> 6) * 8;

    for (int t = 0; t < ntiles; ++t) {
        const int j0 = t * 64;
        const float* kb = qkv + (size_t)(b * Sq + j0) * rs + Dm + h * DHd;
        const float* vb = kb + Dm;

#pragma unroll
        for (int i = 0; i < 8; ++i) {
            int v = tid + i * 128;
            int row = v >> 4, c4 = v & 15;
            float4 k4 = *(const float4*)(kb + (size_t)row * rs + c4 * 4);
            k4.x = tf32r(k4.x); k4.y = tf32r(k4.y);
            k4.z = tf32r(k4.z); k4.w = tf32r(k4.w);
            *(float4*)(sK + row * 68 + c4 * 4) = k4;
        }
        const float* vrow = vb + (size_t)rv * rs + ch * 4;
#pragma unroll
        for (int j = 0; j < 8; ++j) {
            const int c4 = ch + j;
            float4 v4 = *(const float4*)(vrow + j * 4);
            sVt[(c4 * 4 + 0) * 72 + rv] = tf32r(v4.x);
            sVt[(c4 * 4 + 1) * 72 + rv] = tf32r(v4.y);
            sVt[(c4 * 4 + 2) * 72 + rv] = tf32r(v4.z);
            sVt[(c4 * 4 + 3) * 72 + rv] = tf32r(v4.w);
        }
        __syncthreads();

        float sacc[2][8][4];
#pragma unroll
        for (int mt = 0; mt < 2; ++mt)
#pragma unroll
            for (int nt = 0; nt < 8; ++nt)
#pragma unroll
                for (int e = 0; e < 4; ++e) sacc[mt][nt][e] = 0.f;

#pragma unroll
        for (int nt = 0; nt < 8; ++nt) {
            const int krow = (nt * 8 + gid) * 68;
#pragma unroll
            for (int kt = 0; kt < 8; ++kt) {
                uint32_t kf[2];
                kf[0] = __float_as_uint(sK[krow + kt * 8 + tig]);
                kf[1] = __float_as_uint(sK[krow + kt * 8 + tig + 4]);
                mma_tf32(sacc[0][nt], qa[0][kt], kf);
                mma_tf32(sacc[1][nt], qa[1][kt], kf);
            }
        }

        if (j0 + 63 > qr0) {
#pragma unroll
            for (int mt = 0; mt < 2; ++mt) {
                const int r0 = qr0 + wid * 32 + mt * 16 + gid;
#pragma unroll
                for (int nt = 0; nt < 8; ++nt) {
                    const int c = j0 + nt * 8 + 2 * tig;
                    if (c > r0)         sacc[mt][nt][0] = -1e30f;
                    if (c + 1 > r0)     sacc[mt][nt][1] = -1e30f;
                    if (c > r0 + 8)     sacc[mt][nt][2] = -1e30f;
                    if (c + 1 > r0 + 8) sacc[mt][nt][3] = -1e30f;
                }
            }
        }

#pragma unroll
        for (int mt = 0; mt < 2; ++mt) {
#pragma unroll
            for (int hf = 0; hf < 2; ++hf) {
                float mx = mrow[mt][hf];
#pragma unroll
                for (int nt = 0; nt < 8; ++nt)
                    mx = fmaxf(mx, fmaxf(sacc[mt][nt][hf * 2],
                                         sacc[mt][nt][hf * 2 + 1]));
                mx = fmaxf(mx, __shfl_xor_sync(0xffffffffu, mx, 1));
                mx = fmaxf(mx, __shfl_xor_sync(0xffffffffu, mx, 2));
                const float alpha = __expf(mrow[mt][hf] - mx);
                mrow[mt][hf] = mx;
                float lsum = lrow[mt][hf] * alpha;
#pragma unroll
                for (int nt = 0; nt < 8; ++nt) {
                    float p0 = __expf(sacc[mt][nt][hf * 2] - mx);
                    float p1 = __expf(sacc[mt][nt][hf * 2 + 1] - mx);
                    sacc[mt][nt][hf * 2] = p0;
                    sacc[mt][nt][hf * 2 + 1] = p1;
                    lsum += p0 + p1;
                }
                lrow[mt][hf] = lsum;
#pragma unroll
                for (int dt = 0; dt < 8; ++dt) {
                    oacc[mt][dt][hf * 2]     *= alpha;
                    oacc[mt][dt][hf * 2 + 1] *= alpha;
                }
            }
        }

#pragma unroll
        for (int dt = 0; dt < 8; ++dt) {
            const int vrow2 = (dt * 8 + gid) * 72;
#pragma unroll
            for (int kt = 0; kt < 8; ++kt) {
                float2 vv = *(const float2*)(sVt + vrow2 + kt * 8 + 2 * tig);
                uint32_t vf[2] = {__float_as_uint(vv.x), __float_as_uint(vv.y)};
#pragma unroll
                for (int mt = 0; mt < 2; ++mt) {
                    uint32_t pf[4] = {__float_as_uint(sacc[mt][kt][0]),
                                      __float_as_uint(sacc[mt][kt][2]),
                                      __float_as_uint(sacc[mt][kt][1]),
                                      __float_as_uint(sacc[mt][kt][3])};
                    mma_tf32(oacc[mt][dt], pf, vf);
                }
            }
        }
        __syncthreads();
    }

#pragma unroll
    for (int mt = 0; mt < 2; ++mt)
#pragma unroll
        for (int hf = 0; hf < 2; ++hf) {
            float l = lrow[mt][hf];
            l += __shfl_xor_sync(0xffffffffu, l, 1);
            l += __shfl_xor_sync(0xffffffffu, l, 2);
            lrow[mt][hf] = 1.f / l;
        }

    float* ob = out + (size_t)(b * Sq + qr0) * Dm + h * DHd;
#pragma unroll
    for (int mt = 0; mt < 2; ++mt) {
        const int r0 = wid * 32 + mt * 16 + gid;
#pragma unroll
        for (int dt = 0; dt < 8; ++dt) {
            const int c = dt * 8 + 2 * tig;
            float2 w0, w1;
            w0.x = tf32r(oacc[mt][dt][0] * lrow[mt][0]);
            w0.y = tf32r(oacc[mt][dt][1] * lrow[mt][0]);
            w1.x = tf32r(oacc[mt][dt][2] * lrow[mt][1]);
            w1.y = tf32r(oacc[mt][dt][3] * lrow[mt][1]);
            *(float2*)(ob + (size_t)r0 * Dm + c) = w0;
            *(float2*)(ob + (size_t)(r0 + 8) * Dm + c) = w1;
        }
    }
}

// ---------------------------------------------------------------------------
// Launch
// ---------------------------------------------------------------------------
extern "C" void kernel_launch(void* const* d_in, const int* in_sizes, int n_in,
                              void* d_out, int out_size)
{
    const float* x      = (const float*)d_in[0];  // [B,S,D]
    const float* w_attn = (const float*)d_in[1];  // [D,3D]
    const float* b_attn = (const float*)d_in[2];  // [3D]
    const float* w_proj = (const float*)d_in[3];  // [D,D]
    const float* b_proj = (const float*)d_in[4];  // [D]
    float* out = (float*)d_out;

    float *qkv, *attn, *xc, *wat, *wpt;
    cudaGetSymbolAddress((void**)&qkv,  g_qkv);
    cudaGetSymbolAddress((void**)&attn, g_attn);
    cudaGetSymbolAddress((void**)&xc,   g_xc);
    cudaGetSymbolAddress((void**)&wat,  g_wat);
    cudaGetSymbolAddress((void**)&wpt,  g_wpt);

    // 0) tf32 rounding / weight transposes
    cvt_tf32_kernel<<<(Mrows * Dm) / (4 * 256), 256>>>(x, xc);
    transpose_cvt_kernel<<<dim3(QKVCOLS / 32, Dm / 32), dim3(32, 8)>>>(
        w_attn, wat, Dm, QKVCOLS);
    transpose_cvt_kernel<<<dim3(Dm / 32, Dm / 32), dim3(32, 8)>>>(
        w_proj, wpt, Dm, Dm);

    // 1) QKV projection (mma.sync tf32, 8 warps, 1 barrier/stage)
    gemm_mma_tf32<<<dim3(QKVCOLS / 128, Mrows / 128), 256>>>(
        xc, wat, b_attn, qkv, Mrows, QKVCOLS, Dm);

    // 2) Causal multi-head attention (mma.sync tf32 flash)
    attn_mma_kernel<<<dim3(Sq / 128, Hn, Bsz), 128>>>(qkv, attn);

    // 3) Output projection (mma.sync tf32, 8 warps, 1 barrier/stage)
    gemm_mma_tf32<<<dim3(Dm / 128, Mrows / 128), 256>>>(
        attn, wpt, b_proj, out, Mrows, Dm, Dm);
}

// round 9
// speedup vs baseline: 1.0790x; 1.0314x over previous
#include <cuda_runtime.h>
#include <math.h>
#include <stdint.h>

// Problem constants
#define Bsz 4
#define Sq  2048
#define Dm  1024
#define Hn  16
#define DHd 64
#define Mrows (Bsz * Sq)          // 8192
#define QKVCOLS (3 * Dm)          // 3072

// Scratch (allocation-free rule: __device__ globals)
__device__ float g_qkv[(size_t)Mrows * QKVCOLS];   // [8192, 3072] : Q|K|V
__device__ float g_attn[(size_t)Mrows * Dm];       // [8192, 1024] merged heads
__device__ float g_xc [(size_t)Mrows * Dm];        // x rounded to tf32
__device__ float g_wat[(size_t)QKVCOLS * Dm];      // w_attn^T [3072,1024] tf32
__device__ float g_wpt[(size_t)Dm * Dm];           // w_proj^T [1024,1024] tf32

// ---------------------------------------------------------------------------
// helpers
// ---------------------------------------------------------------------------
__device__ __forceinline__ float tf32r(float x) {
    uint32_t u;
    asm("cvt.rna.tf32.f32 %0, %1;" : "=r"(u) : "f"(x));
    return __uint_as_float(u);
}
__device__ __forceinline__ uint32_t tf32u(float x) {
    uint32_t u;
    asm("cvt.rna.tf32.f32 %0, %1;" : "=r"(u) : "f"(x));
    return u;
}
__device__ __forceinline__ uint32_t smem_u32(const void* p) {
    uint32_t a;
    asm("{ .reg .u64 t; cvta.to.shared.u64 t, %1; cvt.u32.u64 %0, t; }"
        : "=r"(a) : "l"(p));
    return a;
}

__device__ __forceinline__ void mma_tf32(float (&d)[4],
                                         const uint32_t (&a)[4],
                                         const uint32_t (&b)[2]) {
    asm volatile(
        "mma.sync.aligned.m16n8k8.row.col.f32.tf32.tf32.f32 "
        "{%0,%1,%2,%3}, {%4,%5,%6,%7}, {%8,%9}, {%0,%1,%2,%3};"
        : "+f"(d[0]), "+f"(d[1]), "+f"(d[2]), "+f"(d[3])
        : "r"(a[0]), "r"(a[1]), "r"(a[2]), "r"(a[3]), "r"(b[0]), "r"(b[1]));
}

#define LDSM4(r, addr) \
    asm volatile("ldmatrix.sync.aligned.m8n8.x4.shared.b16 {%0,%1,%2,%3}, [%4];" \
        : "=r"((r)[0]), "=r"((r)[1]), "=r"((r)[2]), "=r"((r)[3]) : "r"(addr))

#define CP_ASYNC16(dst, src) \
    asm volatile("cp.async.cg.shared.global [%0], [%1], 16;" :: "r"(dst), "l"(src))
#define CP_COMMIT()  asm volatile("cp.async.commit_group;")
#define CP_WAIT1()   asm volatile("cp.async.wait_group 1;")

// ---------------------------------------------------------------------------
// Elementwise round-to-tf32 (float4)
// ---------------------------------------------------------------------------
__global__ __launch_bounds__(256)
void cvt_tf32_kernel(const float* __restrict__ in, float* __restrict__ out) {
    int i = blockIdx.x * 256 + threadIdx.x;
    float4 v = ((const float4*)in)[i];
    v.x = tf32r(v.x); v.y = tf32r(v.y); v.z = tf32r(v.z); v.w = tf32r(v.w);
    ((float4*)out)[i] = v;
}

// ---------------------------------------------------------------------------
// Transpose + round-to-tf32: in[R][C] -> out[C][R]
// ---------------------------------------------------------------------------
__global__ __launch_bounds__(256)
void transpose_cvt_kernel(const float* __restrict__ in, float* __restrict__ out,
                          int R, int C) {
    __shared__ float t[32][33];
    const int c0 = blockIdx.x * 32, r0 = blockIdx.y * 32;
    const int tx = threadIdx.x, ty = threadIdx.y;   // 32 x 8
#pragma unroll
    for (int i = 0; i < 32; i += 8)
        t[ty + i][tx] = tf32r(in[(size_t)(r0 + ty + i) * C + c0 + tx]);
    __syncthreads();
#pragma unroll
    for (int i = 0; i < 32; i += 8)
        out[(size_t)(c0 + ty + i) * R + r0 + tx] = t[tx][ty + i];
}

// ---------------------------------------------------------------------------
// tf32 GEMM v5: C[M,N] = A[M,K] @ BT[N,K]^T + bias[N]
// CTA 128x128, 8 warps (2m x 4n), warp tile 64x32.
// k-stage 32 (row = 32 floats = 128B; quad q stored at q ^ (row&7)),
// 3-stage cp.async pipeline in 96KB DYNAMIC smem, ldmatrix.x4 frags,
// one __syncthreads per stage. 64 MMAs per warp per barrier.
// ---------------------------------------------------------------------------
#define GSTAGE 16384u   // bytes per matrix per stage (128 x 32 x 4)

__global__ __launch_bounds__(256, 2)
void gemm_mma_tf32(const float* __restrict__ A, const float* __restrict__ BT,
                   const float* __restrict__ bias, float* __restrict__ C,
                   int M, int N, int K)
{
    extern __shared__ __align__(16) float dynsm[];
    const uint32_t sAaddr = smem_u32(dynsm);             // 3 stages A
    const uint32_t sBaddr = sAaddr + 3u * GSTAGE;        // 3 stages B

    const int tid  = threadIdx.x;
    const int wid  = tid >> 5;
    const int lane = tid & 31;
    const int gid  = lane >> 2;
    const int tig  = lane & 3;
    const int wm   = wid & 1;        // 0..1 -> 64 rows
    const int wn   = wid >> 1;       // 0..3 -> 32 cols
    const int m0   = blockIdx.y * 128;
    const int n0   = blockIdx.x * 128;

    // --- staging: thread covers rows (tid>>3)+32i, quad tid&7, i=0..3 ---
    // row+32i has same (row&7); slot_i = slot_0 + i*4096B; gmem + i*32*K
    const int srow = tid >> 3;       // 0..31
    const int sq   = tid & 7;
    const uint32_t slotB = (uint32_t)(srow * 32 + ((sq ^ (srow & 7)) << 2)) * 4u;
    const float* aP = A  + (size_t)(m0 + srow) * K + sq * 4;
    const float* bP = BT + (size_t)(n0 + srow) * K + sq * 4;
    const size_t rstep = (size_t)32 * K;

    // --- ldmatrix per-lane address components ---
    const int lrow = lane & 15;            // row within 16-row block
    const int kh   = (lane >> 4) & 1;      // k-half select
    uint32_t aoff[4], boff[2];
    int xa[4], xb[2];
#pragma unroll
    for (int i = 0; i < 4; ++i) {
        int ra = wm * 64 + i * 16 + lrow;
        aoff[i] = (uint32_t)ra * 128u;   // bytes (32 floats/row)
        xa[i] = ra & 7;
    }
#pragma unroll
    for (int i = 0; i < 2; ++i) {
        int rb = wn * 32 + i * 16 + lrow;
        boff[i] = (uint32_t)rb * 128u;
        xb[i] = rb & 7;
    }

    float acc[4][4][4];
#pragma unroll
    for (int mt = 0; mt < 4; ++mt)
#pragma unroll
        for (int nt = 0; nt < 4; ++nt)
#pragma unroll
            for (int e = 0; e < 4; ++e) acc[mt][nt][e] = 0.f;

    const int nst = K / 32;

    // --- prologue: stages 0,1 in flight (stage s -> buffer s%3) ---
#pragma unroll
    for (int s = 0; s < 2; ++s) {
        const uint32_t da = sAaddr + s * GSTAGE + slotB;
        const uint32_t db = sBaddr + s * GSTAGE + slotB;
        const int ko = s * 32;
#pragma unroll
        for (int i = 0; i < 4; ++i) {
            CP_ASYNC16(da + i * 4096u, aP + i * rstep + ko);
            CP_ASYNC16(db + i * 4096u, bP + i * rstep + ko);
        }
        CP_COMMIT();
    }

    int buf = 0;
    for (int s = 0; s < nst; ++s) {
        CP_WAIT1();
        __syncthreads();

        const uint32_t aB = sAaddr + buf * GSTAGE;
        const uint32_t bB = sBaddr + buf * GSTAGE;

        // stage s+2 -> buffer (s+2)%3 == (s-1)%3 (reads done pre-barrier).
        // Commit ALWAYS (empty tail groups keep wait_group 1 sound).
        if (s + 2 < nst) {
            const int wb = (buf + 2) % 3;
            const uint32_t da = sAaddr + wb * GSTAGE + slotB;
            const uint32_t db = sBaddr + wb * GSTAGE + slotB;
            const int ko = (s + 2) * 32;
#pragma unroll
            for (int i = 0; i < 4; ++i) {
                CP_ASYNC16(da + i * 4096u, aP + i * rstep + ko);
                CP_ASYNC16(db + i * 4096u, bP + i * rstep + ko);
            }
        }
        CP_COMMIT();

#pragma unroll
        for (int kt = 0; kt < 4; ++kt) {
            const int kq = kt * 2 + kh;       // quad 0..7 within 32-float row
            uint32_t af[4][4], bm[2][4];
#pragma unroll
            for (int mt = 0; mt < 4; ++mt)
                LDSM4(af[mt], aB + aoff[mt] + (uint32_t)((kq ^ xa[mt]) << 4));
#pragma unroll
            for (int p = 0; p < 2; ++p)
                LDSM4(bm[p], bB + boff[p] + (uint32_t)((kq ^ xb[p]) << 4));
#pragma unroll
            for (int nt = 0; nt < 4; ++nt) {
                uint32_t bfr[2] = { bm[nt >> 1][nt & 1], bm[nt >> 1][2 + (nt & 1)] };
#pragma unroll
                for (int mt = 0; mt < 4; ++mt)
                    mma_tf32(acc[mt][nt], af[mt], bfr);
            }
        }

        buf = (buf == 2) ? 0 : buf + 1;
    }

    // Epilogue: + bias, store
#pragma unroll
    for (int mt = 0; mt < 4; ++mt) {
        const int r = m0 + wm * 64 + mt * 16 + gid;
#pragma unroll
        for (int nt = 0; nt < 4; ++nt) {
            const int c = n0 + wn * 32 + nt * 8 + tig * 2;
            float b0 = bias[c], b1 = bias[c + 1];
            float2 v0 = make_float2(acc[mt][nt][0] + b0, acc[mt][nt][1] + b1);
            float2 v1 = make_float2(acc[mt][nt][2] + b0, acc[mt][nt][3] + b1);
            *(float2*)&C[(size_t)r * N + c] = v0;
            *(float2*)&C[(size_t)(r + 8) * N + c] = v1;
        }
    }
}

// ---------------------------------------------------------------------------
// Flash attention, mma.sync tf32. CTA = (b, h, 128 q-rows), 8 warps (256 thr),
// each warp owns 16 q rows (one m16 block) -> ~120 live regs, 2 CTA/SM,
// 16 warps/SM (2x the old occupancy). Same tiles/math as before.
// ---------------------------------------------------------------------------
__global__ __launch_bounds__(256, 2)
void attn_mma_kernel(const float* __restrict__ qkv, float* __restrict__ out)
{
    __shared__ __align__(16) float sm[64 * 68 + 64 * 72];  // 35840 B
    float* sK  = sm;             // [64 key][68]
    float* sVt = sm + 64 * 68;   // [64 dh][72]

    const int tid  = threadIdx.x;
    const int wid  = tid >> 5;          // 0..7
    const int lane = tid & 31;
    const int gid  = lane >> 2;
    const int tig  = lane & 3;
    const int h    = blockIdx.y;
    const int b    = blockIdx.z;
    const int qr0  = blockIdx.x * 128;

    const size_t rs = (size_t)QKVCOLS;
    const float* qbase = qkv + (size_t)(b * Sq + qr0) * rs + h * DHd;

    // --- stage Q [128][64] into smem (stride 68): 2048 float4 / 256 thr ---
#pragma unroll
    for (int i = 0; i < 8; ++i) {
        int v = tid + i * 256;
        int row = v >> 4, c4 = v & 15;
        float4 q4 = *(const float4*)(qbase + (size_t)row * rs + c4 * 4);
        *(float4*)(sm + row * 68 + c4 * 4) = q4;
    }
    __syncthreads();

    // --- Q fragments: warp owns rows wid*16 .. wid*16+15 ---
    uint32_t qa[8][4];
    {
        const int r0 = wid * 16 + gid;
#pragma unroll
        for (int kt = 0; kt < 8; ++kt) {
            const int c = kt * 8 + tig;
            qa[kt][0] = tf32u(sm[r0 * 68 + c] * 0.125f);
            qa[kt][1] = tf32u(sm[(r0 + 8) * 68 + c] * 0.125f);
            qa[kt][2] = tf32u(sm[r0 * 68 + c + 4] * 0.125f);
            qa[kt][3] = tf32u(sm[(r0 + 8) * 68 + c + 4] * 0.125f);
        }
    }
    __syncthreads();

    float oacc[8][4];
#pragma unroll
    for (int dt = 0; dt < 8; ++dt)
#pragma unroll
        for (int e = 0; e < 4; ++e) oacc[dt][e] = 0.f;
    float mrow[2] = {-1e30f, -1e30f};
    float lrow[2] = {0.f, 0.f};

    const int ntiles = qr0 / 64 + 2;
    const int rv = tid & 63;            // V^T staging: key row
    const int ch = (tid >> 6) * 4;      // 4 dh-quads per thread

    for (int t = 0; t < ntiles; ++t) {
        const int j0 = t * 64;
        const float* kb = qkv + (size_t)(b * Sq + j0) * rs + Dm + h * DHd;
        const float* vb = kb + Dm;

        // stage K rows (rounded): 1024 float4 / 256 thr
#pragma unroll
        for (int i = 0; i < 4; ++i) {
            int v = tid + i * 256;
            int row = v >> 4, c4 = v & 15;
            float4 k4 = *(const float4*)(kb + (size_t)row * rs + c4 * 4);
            k4.x = tf32r(k4.x); k4.y = tf32r(k4.y);
            k4.z = tf32r(k4.z); k4.w = tf32r(k4.w);
            *(float4*)(sK + row * 68 + c4 * 4) = k4;
        }
        // stage V^T: lane varies key-row -> conflict-free scalar STS
        const float* vrow = vb + (size_t)rv * rs + ch * 4;
#pragma unroll
        for (int j = 0; j < 4; ++j) {
            const int c4 = ch + j;
            float4 v4 = *(const float4*)(vrow + j * 4);
            sVt[(c4 * 4 + 0) * 72 + rv] = tf32r(v4.x);
            sVt[(c4 * 4 + 1) * 72 + rv] = tf32r(v4.y);
            sVt[(c4 * 4 + 2) * 72 + rv] = tf32r(v4.z);
            sVt[(c4 * 4 + 3) * 72 + rv] = tf32r(v4.w);
        }
        __syncthreads();

        // --- S = Q @ K^T ---
        float sacc[8][4];
#pragma unroll
        for (int nt = 0; nt < 8; ++nt)
#pragma unroll
            for (int e = 0; e < 4; ++e) sacc[nt][e] = 0.f;

#pragma unroll
        for (int nt = 0; nt < 8; ++nt) {
            const int krow = (nt * 8 + gid) * 68;
#pragma unroll
            for (int kt = 0; kt < 8; ++kt) {
                uint32_t kf[2];
                kf[0] = __float_as_uint(sK[krow + kt * 8 + tig]);
                kf[1] = __float_as_uint(sK[krow + kt * 8 + tig + 4]);
                mma_tf32(sacc[nt], qa[kt], kf);
            }
        }

        // --- causal mask (boundary tiles only) ---
        if (j0 + 63 > qr0) {
            const int r0 = qr0 + wid * 16 + gid;
#pragma unroll
            for (int nt = 0; nt < 8; ++nt) {
                const int c = j0 + nt * 8 + 2 * tig;
                if (c > r0)         sacc[nt][0] = -1e30f;
                if (c + 1 > r0)     sacc[nt][1] = -1e30f;
                if (c > r0 + 8)     sacc[nt][2] = -1e30f;
                if (c + 1 > r0 + 8) sacc[nt][3] = -1e30f;
            }
        }

        // --- online softmax, P left in sacc ---
#pragma unroll
        for (int hf = 0; hf < 2; ++hf) {
            float mx = mrow[hf];
#pragma unroll
            for (int nt = 0; nt < 8; ++nt)
                mx = fmaxf(mx, fmaxf(sacc[nt][hf * 2], sacc[nt][hf * 2 + 1]));
            mx = fmaxf(mx, __shfl_xor_sync(0xffffffffu, mx, 1));
            mx = fmaxf(mx, __shfl_xor_sync(0xffffffffu, mx, 2));
            const float alpha = __expf(mrow[hf] - mx);
            mrow[hf] = mx;
            float lsum = lrow[hf] * alpha;
#pragma unroll
            for (int nt = 0; nt < 8; ++nt) {
                float p0 = __expf(sacc[nt][hf * 2] - mx);
                float p1 = __expf(sacc[nt][hf * 2 + 1] - mx);
                sacc[nt][hf * 2] = p0;
                sacc[nt][hf * 2 + 1] = p1;
                lsum += p0 + p1;
            }
            lrow[hf] = lsum;
#pragma unroll
            for (int dt = 0; dt < 8; ++dt) {
                oacc[dt][hf * 2]     *= alpha;
                oacc[dt][hf * 2 + 1] *= alpha;
            }
        }

        // --- O += P @ V (key perm absorbed in Vt) ---
#pragma unroll
        for (int dt = 0; dt < 8; ++dt) {
            const int vrow2 = (dt * 8 + gid) * 72;
#pragma unroll
            for (int kt = 0; kt < 8; ++kt) {
                float2 vv = *(const float2*)(sVt + vrow2 + kt * 8 + 2 * tig);
                uint32_t vf[2] = {__float_as_uint(vv.x), __float_as_uint(vv.y)};
                uint32_t pf[4] = {__float_as_uint(sacc[kt][0]),
                                  __float_as_uint(sacc[kt][2]),
                                  __float_as_uint(sacc[kt][1]),
                                  __float_as_uint(sacc[kt][3])};
                mma_tf32(oacc[dt], pf, vf);
            }
        }
        __syncthreads();
    }

    // --- epilogue ---
#pragma unroll
    for (int hf = 0; hf < 2; ++hf) {
        float l = lrow[hf];
        l += __shfl_xor_sync(0xffffffffu, l, 1);
        l += __shfl_xor_sync(0xffffffffu, l, 2);
        lrow[hf] = 1.f / l;
    }

    float* ob = out + (size_t)(b * Sq + qr0) * Dm + h * DHd;
    {
        const int r0 = wid * 16 + gid;
#pragma unroll
        for (int dt = 0; dt < 8; ++dt) {
            const int c = dt * 8 + 2 * tig;
            float2 w0, w1;
            w0.x = tf32r(oacc[dt][0] * lrow[0]);
            w0.y = tf32r(oacc[dt][1] * lrow[0]);
            w1.x = tf32r(oacc[dt][2] * lrow[1]);
            w1.y = tf32r(oacc[dt][3] * lrow[1]);
            *(float2*)(ob + (size_t)r0 * Dm + c) = w0;
            *(float2*)(ob + (size_t)(r0 + 8) * Dm + c) = w1;
        }
    }
}

// ---------------------------------------------------------------------------
// Launch
// ---------------------------------------------------------------------------
extern "C" void kernel_launch(void* const* d_in, const int* in_sizes, int n_in,
                              void* d_out, int out_size)
{
    const float* x      = (const float*)d_in[0];  // [B,S,D]
    const float* w_attn = (const float*)d_in[1];  // [D,3D]
    const float* b_attn = (const float*)d_in[2];  // [3D]
    const float* w_proj = (const float*)d_in[3];  // [D,D]
    const float* b_proj = (const float*)d_in[4];  // [D]
    float* out = (float*)d_out;

    float *qkv, *attn, *xc, *wat, *wpt;
    cudaGetSymbolAddress((void**)&qkv,  g_qkv);
    cudaGetSymbolAddress((void**)&attn, g_attn);
    cudaGetSymbolAddress((void**)&xc,   g_xc);
    cudaGetSymbolAddress((void**)&wat,  g_wat);
    cudaGetSymbolAddress((void**)&wpt,  g_wpt);

    // Allow 96KB dynamic smem for the GEMM (idempotent, non-captured call)
    const int GEMM_SMEM = 6 * (int)GSTAGE;   // 98304
    cudaFuncSetAttribute(gemm_mma_tf32,
                         cudaFuncAttributeMaxDynamicSharedMemorySize, GEMM_SMEM);

    // 0) tf32 rounding / weight transposes
    cvt_tf32_kernel<<<(Mrows * Dm) / (4 * 256), 256>>>(x, xc);
    transpose_cvt_kernel<<<dim3(QKVCOLS / 32, Dm / 32), dim3(32, 8)>>>(
        w_attn, wat, Dm, QKVCOLS);
    transpose_cvt_kernel<<<dim3(Dm / 32, Dm / 32), dim3(32, 8)>>>(
        w_proj, wpt, Dm, Dm);

    // 1) QKV projection (mma.sync tf32, k-stage 32, 96KB smem pipeline)
    gemm_mma_tf32<<<dim3(QKVCOLS / 128, Mrows / 128), 256, GEMM_SMEM>>>(
        xc, wat, b_attn, qkv, Mrows, QKVCOLS, Dm);

    // 2) Causal multi-head attention (mma.sync tf32 flash, 8 warps/CTA)
    attn_mma_kernel<<<dim3(Sq / 128, Hn, Bsz), 256>>>(qkv, attn);

    // 3) Output projection
    gemm_mma_tf32<<<dim3(Dm / 128, Mrows / 128), 256, GEMM_SMEM>>>(
        attn, wpt, b_proj, out, Mrows, Dm, Dm);
}

// round 10
// speedup vs baseline: 1.0851x; 1.0057x over previous
#include <cuda_runtime.h>
#include <math.h>
#include <stdint.h>

// Problem constants
#define Bsz 4
#define Sq  2048
#define Dm  1024
#define Hn  16
#define DHd 64
#define Mrows (Bsz * Sq)          // 8192
#define QKVCOLS (3 * Dm)          // 3072

// Scratch (allocation-free rule: __device__ globals)
__device__ float g_qkv[(size_t)Mrows * QKVCOLS];   // [8192, 3072] : Q|K|V
__device__ float g_attn[(size_t)Mrows * Dm];       // [8192, 1024] merged heads
__device__ float g_xc [(size_t)Mrows * Dm];        // x rounded to tf32
__device__ float g_wat[(size_t)QKVCOLS * Dm];      // w_attn^T [3072,1024] tf32
__device__ float g_wpt[(size_t)Dm * Dm];           // w_proj^T [1024,1024] tf32

// ---------------------------------------------------------------------------
// helpers
// ---------------------------------------------------------------------------
__device__ __forceinline__ float tf32r(float x) {
    uint32_t u;
    asm("cvt.rna.tf32.f32 %0, %1;" : "=r"(u) : "f"(x));
    return __uint_as_float(u);
}
__device__ __forceinline__ uint32_t tf32u(float x) {
    uint32_t u;
    asm("cvt.rna.tf32.f32 %0, %1;" : "=r"(u) : "f"(x));
    return u;
}
__device__ __forceinline__ uint32_t smem_u32(const void* p) {
    uint32_t a;
    asm("{ .reg .u64 t; cvta.to.shared.u64 t, %1; cvt.u32.u64 %0, t; }"
        : "=r"(a) : "l"(p));
    return a;
}

__device__ __forceinline__ void mma_tf32(float (&d)[4],
                                         const uint32_t (&a)[4],
                                         const uint32_t (&b)[2]) {
    asm volatile(
        "mma.sync.aligned.m16n8k8.row.col.f32.tf32.tf32.f32 "
        "{%0,%1,%2,%3}, {%4,%5,%6,%7}, {%8,%9}, {%0,%1,%2,%3};"
        : "+f"(d[0]), "+f"(d[1]), "+f"(d[2]), "+f"(d[3])
        : "r"(a[0]), "r"(a[1]), "r"(a[2]), "r"(a[3]), "r"(b[0]), "r"(b[1]));
}

#define LDSM4(r, addr) \
    asm volatile("ldmatrix.sync.aligned.m8n8.x4.shared.b16 {%0,%1,%2,%3}, [%4];" \
        : "=r"((r)[0]), "=r"((r)[1]), "=r"((r)[2]), "=r"((r)[3]) : "r"(addr))

#define CP_ASYNC16(dst, src) \
    asm volatile("cp.async.cg.shared.global [%0], [%1], 16;" :: "r"(dst), "l"(src))
#define CP_COMMIT()  asm volatile("cp.async.commit_group;")
#define CP_WAIT1()   asm volatile("cp.async.wait_group 1;")

// ---------------------------------------------------------------------------
// Elementwise round-to-tf32 (float4)
// ---------------------------------------------------------------------------
__global__ __launch_bounds__(256)
void cvt_tf32_kernel(const float* __restrict__ in, float* __restrict__ out) {
    int i = blockIdx.x * 256 + threadIdx.x;
    float4 v = ((const float4*)in)[i];
    v.x = tf32r(v.x); v.y = tf32r(v.y); v.z = tf32r(v.z); v.w = tf32r(v.w);
    ((float4*)out)[i] = v;
}

// ---------------------------------------------------------------------------
// Transpose + round-to-tf32: in[R][C] -> out[C][R]
// ---------------------------------------------------------------------------
__global__ __launch_bounds__(256)
void transpose_cvt_kernel(const float* __restrict__ in, float* __restrict__ out,
                          int R, int C) {
    __shared__ float t[32][33];
    const int c0 = blockIdx.x * 32, r0 = blockIdx.y * 32;
    const int tx = threadIdx.x, ty = threadIdx.y;   // 32 x 8
#pragma unroll
    for (int i = 0; i < 32; i += 8)
        t[ty + i][tx] = tf32r(in[(size_t)(r0 + ty + i) * C + c0 + tx]);
    __syncthreads();
#pragma unroll
    for (int i = 0; i < 32; i += 8)
        out[(size_t)(c0 + ty + i) * R + r0 + tx] = t[tx][ty + i];
}

// ---------------------------------------------------------------------------
// tf32 GEMM v5 (unchanged from round 9): CTA 128x128, 8 warps, k-stage 32,
// 3-stage cp.async pipeline in 96KB dynamic smem, ldmatrix.x4 frags.
// ---------------------------------------------------------------------------
#define GSTAGE 16384u   // bytes per matrix per stage (128 x 32 x 4)

__global__ __launch_bounds__(256, 2)
void gemm_mma_tf32(const float* __restrict__ A, const float* __restrict__ BT,
                   const float* __restrict__ bias, float* __restrict__ C,
                   int M, int N, int K)
{
    extern __shared__ __align__(16) float dynsm[];
    const uint32_t sAaddr = smem_u32(dynsm);             // 3 stages A
    const uint32_t sBaddr = sAaddr + 3u * GSTAGE;        // 3 stages B

    const int tid  = threadIdx.x;
    const int wid  = tid >> 5;
    const int lane = tid & 31;
    const int gid  = lane >> 2;
    const int tig  = lane & 3;
    const int wm   = wid & 1;
    const int wn   = wid >> 1;
    const int m0   = blockIdx.y * 128;
    const int n0   = blockIdx.x * 128;

    const int srow = tid >> 3;       // 0..31
    const int sq   = tid & 7;
    const uint32_t slotB = (uint32_t)(srow * 32 + ((sq ^ (srow & 7)) << 2)) * 4u;
    const float* aP = A  + (size_t)(m0 + srow) * K + sq * 4;
    const float* bP = BT + (size_t)(n0 + srow) * K + sq * 4;
    const size_t rstep = (size_t)32 * K;

    const int lrow = lane & 15;
    const int kh   = (lane >> 4) & 1;
    uint32_t aoff[4], boff[2];
    int xa[4], xb[2];
#pragma unroll
    for (int i = 0; i < 4; ++i) {
        int ra = wm * 64 + i * 16 + lrow;
        aoff[i] = (uint32_t)ra * 128u;
        xa[i] = ra & 7;
    }
#pragma unroll
    for (int i = 0; i < 2; ++i) {
        int rb = wn * 32 + i * 16 + lrow;
        boff[i] = (uint32_t)rb * 128u;
        xb[i] = rb & 7;
    }

    float acc[4][4][4];
#pragma unroll
    for (int mt = 0; mt < 4; ++mt)
#pragma unroll
        for (int nt = 0; nt < 4; ++nt)
#pragma unroll
            for (int e = 0; e < 4; ++e) acc[mt][nt][e] = 0.f;

    const int nst = K / 32;

#pragma unroll
    for (int s = 0; s < 2; ++s) {
        const uint32_t da = sAaddr + s * GSTAGE + slotB;
        const uint32_t db = sBaddr + s * GSTAGE + slotB;
        const int ko = s * 32;
#pragma unroll
        for (int i = 0; i < 4; ++i) {
            CP_ASYNC16(da + i * 4096u, aP + i * rstep + ko);
            CP_ASYNC16(db + i * 4096u, bP + i * rstep + ko);
        }
        CP_COMMIT();
    }

    int buf = 0;
    for (int s = 0; s < nst; ++s) {
        CP_WAIT1();
        __syncthreads();

        const uint32_t aB = sAaddr + buf * GSTAGE;
        const uint32_t bB = sBaddr + buf * GSTAGE;

        if (s + 2 < nst) {
            const int wb = (buf + 2) % 3;
            const uint32_t da = sAaddr + wb * GSTAGE + slotB;
            const uint32_t db = sBaddr + wb * GSTAGE + slotB;
            const int ko = (s + 2) * 32;
#pragma unroll
            for (int i = 0; i < 4; ++i) {
                CP_ASYNC16(da + i * 4096u, aP + i * rstep + ko);
                CP_ASYNC16(db + i * 4096u, bP + i * rstep + ko);
            }
        }
        CP_COMMIT();

#pragma unroll
        for (int kt = 0; kt < 4; ++kt) {
            const int kq = kt * 2 + kh;
            uint32_t af[4][4], bm[2][4];
#pragma unroll
            for (int mt = 0; mt < 4; ++mt)
                LDSM4(af[mt], aB + aoff[mt] + (uint32_t)((kq ^ xa[mt]) << 4));
#pragma unroll
            for (int p = 0; p < 2; ++p)
                LDSM4(bm[p], bB + boff[p] + (uint32_t)((kq ^ xb[p]) << 4));
#pragma unroll
            for (int nt = 0; nt < 4; ++nt) {
                uint32_t bfr[2] = { bm[nt >> 1][nt & 1], bm[nt >> 1][2 + (nt & 1)] };
#pragma unroll
                for (int mt = 0; mt < 4; ++mt)
                    mma_tf32(acc[mt][nt], af[mt], bfr);
            }
        }

        buf = (buf == 2) ? 0 : buf + 1;
    }

#pragma unroll
    for (int mt = 0; mt < 4; ++mt) {
        const int r = m0 + wm * 64 + mt * 16 + gid;
#pragma unroll
        for (int nt = 0; nt < 4; ++nt) {
            const int c = n0 + wn * 32 + nt * 8 + tig * 2;
            float b0 = bias[c], b1 = bias[c + 1];
            float2 v0 = make_float2(acc[mt][nt][0] + b0, acc[mt][nt][1] + b1);
            float2 v1 = make_float2(acc[mt][nt][2] + b0, acc[mt][nt][3] + b1);
            *(float2*)&C[(size_t)r * N + c] = v0;
            *(float2*)&C[(size_t)(r + 8) * N + c] = v1;
        }
    }
}

// ---------------------------------------------------------------------------
// Flash attention v3: mma.sync tf32 + ldmatrix fragment loads.
// CTA = (b, h, 128 q-rows), 8 warps (256 thr), warp owns 16 q rows.
// sK  [64 key][64 f] rows 256B, quad q at q^(row&7)  -> K B-frags via LDSM4
// sVt [64 dh ][64 f] same layout, key position permuted within 8-groups
//   (pos = (k>>1)|((k&1)<<2)) so LDSM B-frags match the renamed P A-frags.
// ---------------------------------------------------------------------------
__global__ __launch_bounds__(256, 2)
void attn_mma_kernel(const float* __restrict__ qkv, float* __restrict__ out)
{
    __shared__ __align__(16) float sm[128 * 68];  // 34816B (Q staging / K,V tiles)
    float* sK  = sm;             // 4096 floats
    float* sVt = sm + 4096;      // 4096 floats

    const int tid  = threadIdx.x;
    const int wid  = tid >> 5;          // 0..7
    const int lane = tid & 31;
    const int gid  = lane >> 2;
    const int tig  = lane & 3;
    const int lrow = lane & 15;
    const int kh   = (lane >> 4) & 1;
    const int h    = blockIdx.y;
    const int b    = blockIdx.z;
    const int qr0  = blockIdx.x * 128;

    const size_t rs = (size_t)QKVCOLS;
    const float* qbase = qkv + (size_t)(b * Sq + qr0) * rs + h * DHd;

    // --- stage Q [128][64] (stride 68), extract A-frags ---
#pragma unroll
    for (int i = 0; i < 8; ++i) {
        int v = tid + i * 256;
        int row = v >> 4, c4 = v & 15;
        float4 q4 = *(const float4*)(qbase + (size_t)row * rs + c4 * 4);
        *(float4*)(sm + row * 68 + c4 * 4) = q4;
    }
    __syncthreads();

    uint32_t qa[8][4];
    {
        const int r0 = wid * 16 + gid;
#pragma unroll
        for (int kt = 0; kt < 8; ++kt) {
            const int c = kt * 8 + tig;
            qa[kt][0] = tf32u(sm[r0 * 68 + c] * 0.125f);
            qa[kt][1] = tf32u(sm[(r0 + 8) * 68 + c] * 0.125f);
            qa[kt][2] = tf32u(sm[r0 * 68 + c + 4] * 0.125f);
            qa[kt][3] = tf32u(sm[(r0 + 8) * 68 + c + 4] * 0.125f);
        }
    }
    __syncthreads();

    // LDSM row descriptors (shared by sK and sVt: 256B rows)
    const uint32_t sKaddr = smem_u32(sK);
    const uint32_t sVaddr = smem_u32(sVt);
    uint32_t roff[4]; int xr[4];
#pragma unroll
    for (int p = 0; p < 4; ++p) {
        int r = p * 16 + lrow;
        roff[p] = (uint32_t)r * 256u;
        xr[p] = r & 7;
    }

    float oacc[8][4];
#pragma unroll
    for (int dt = 0; dt < 8; ++dt)
#pragma unroll
        for (int e = 0; e < 4; ++e) oacc[dt][e] = 0.f;
    float mrow[2] = {-1e30f, -1e30f};
    float lrow2[2] = {0.f, 0.f};

    const int ntiles = qr0 / 64 + 2;
    const int rv = tid & 63;                      // V staging: key
    const int ch = (tid >> 6) * 4;                // 4 dh-quads per thread
    const int kp = (rv & 56) | ((rv & 7) >> 1) | ((rv & 1) << 2);  // permuted pos

    for (int t = 0; t < ntiles; ++t) {
        const int j0 = t * 64;
        const float* kb = qkv + (size_t)(b * Sq + j0) * rs + Dm + h * DHd;
        const float* vb = kb + Dm;

        // --- stage K: 64 key rows x 64 floats, quad-swizzled, rounded ---
#pragma unroll
        for (int i = 0; i < 4; ++i) {
            int v = tid + i * 256;
            int row = v >> 4, q = v & 15;
            float4 k4 = *(const float4*)(kb + (size_t)row * rs + q * 4);
            k4.x = tf32r(k4.x); k4.y = tf32r(k4.y);
            k4.z = tf32r(k4.z); k4.w = tf32r(k4.w);
            *(float4*)((char*)sK + row * 256 + ((q ^ (row & 7)) << 4)) = k4;
        }
        // --- stage V^T: dh rows, permuted+swizzled key position, rounded ---
        {
            const float* vrow = vb + (size_t)rv * rs + ch * 4;
#pragma unroll
            for (int j = 0; j < 4; ++j) {
                float4 v4 = *(const float4*)(vrow + j * 4);
                float vals[4] = {tf32r(v4.x), tf32r(v4.y), tf32r(v4.z), tf32r(v4.w)};
#pragma unroll
                for (int u = 0; u < 4; ++u) {
                    const int row = (ch + j) * 4 + u;
                    sVt[row * 64 + ((((kp >> 2) ^ (row & 7)) << 2) | (kp & 3))] = vals[u];
                }
            }
        }
        __syncthreads();

        // --- S = Q @ K^T (K B-frags via LDSM4) ---
        float sacc[8][4];
#pragma unroll
        for (int nt = 0; nt < 8; ++nt)
#pragma unroll
            for (int e = 0; e < 4; ++e) sacc[nt][e] = 0.f;

#pragma unroll
        for (int kt = 0; kt < 8; ++kt) {
            const int kq = kt * 2 + kh;
#pragma unroll
            for (int p = 0; p < 4; ++p) {
                uint32_t km[4];
                LDSM4(km, sKaddr + roff[p] + (uint32_t)((kq ^ xr[p]) << 4));
                uint32_t b0[2] = {km[0], km[2]};
                uint32_t b1[2] = {km[1], km[3]};
                mma_tf32(sacc[2 * p],     qa[kt], b0);
                mma_tf32(sacc[2 * p + 1], qa[kt], b1);
            }
        }

        // --- causal mask (boundary tiles only) ---
        if (j0 + 63 > qr0) {
            const int r0 = qr0 + wid * 16 + gid;
#pragma unroll
            for (int nt = 0; nt < 8; ++nt) {
                const int c = j0 + nt * 8 + 2 * tig;
                if (c > r0)         sacc[nt][0] = -1e30f;
                if (c + 1 > r0)     sacc[nt][1] = -1e30f;
                if (c > r0 + 8)     sacc[nt][2] = -1e30f;
                if (c + 1 > r0 + 8) sacc[nt][3] = -1e30f;
            }
        }

        // --- online softmax, P left in sacc ---
#pragma unroll
        for (int hf = 0; hf < 2; ++hf) {
            float mx = mrow[hf];
#pragma unroll
            for (int nt = 0; nt < 8; ++nt)
                mx = fmaxf(mx, fmaxf(sacc[nt][hf * 2], sacc[nt][hf * 2 + 1]));
            mx = fmaxf(mx, __shfl_xor_sync(0xffffffffu, mx, 1));
            mx = fmaxf(mx, __shfl_xor_sync(0xffffffffu, mx, 2));
            const float alpha = __expf(mrow[hf] - mx);
            mrow[hf] = mx;
            float lsum = lrow2[hf] * alpha;
#pragma unroll
            for (int nt = 0; nt < 8; ++nt) {
                float p0 = __expf(sacc[nt][hf * 2] - mx);
                float p1 = __expf(sacc[nt][hf * 2 + 1] - mx);
                sacc[nt][hf * 2] = p0;
                sacc[nt][hf * 2 + 1] = p1;
                lsum += p0 + p1;
            }
            lrow2[hf] = lsum;
#pragma unroll
            for (int dt = 0; dt < 8; ++dt) {
                oacc[dt][hf * 2]     *= alpha;
                oacc[dt][hf * 2 + 1] *= alpha;
            }
        }

        // --- O += P @ V (V B-frags via LDSM4; perm absorbed at store) ---
#pragma unroll
        for (int kt = 0; kt < 8; ++kt) {
            const int kq = kt * 2 + kh;
            uint32_t pf[4] = {__float_as_uint(sacc[kt][0]),
                              __float_as_uint(sacc[kt][2]),
                              __float_as_uint(sacc[kt][1]),
                              __float_as_uint(sacc[kt][3])};
#pragma unroll
            for (int p = 0; p < 4; ++p) {
                uint32_t vm[4];
                LDSM4(vm, sVaddr + roff[p] + (uint32_t)((kq ^ xr[p]) << 4));
                uint32_t b0[2] = {vm[0], vm[2]};
                uint32_t b1[2] = {vm[1], vm[3]};
                mma_tf32(oacc[2 * p],     pf, b0);
                mma_tf32(oacc[2 * p + 1], pf, b1);
            }
        }
        __syncthreads();
    }

    // --- epilogue ---
#pragma unroll
    for (int hf = 0; hf < 2; ++hf) {
        float l = lrow2[hf];
        l += __shfl_xor_sync(0xffffffffu, l, 1);
        l += __shfl_xor_sync(0xffffffffu, l, 2);
        lrow2[hf] = 1.f / l;
    }

    float* ob = out + (size_t)(b * Sq + qr0) * Dm + h * DHd;
    {
        const int r0 = wid * 16 + gid;
#pragma unroll
        for (int dt = 0; dt < 8; ++dt) {
            const int c = dt * 8 + 2 * tig;
            float2 w0, w1;
            w0.x = tf32r(oacc[dt][0] * lrow2[0]);
            w0.y = tf32r(oacc[dt][1] * lrow2[0]);
            w1.x = tf32r(oacc[dt][2] * lrow2[1]);
            w1.y = tf32r(oacc[dt][3] * lrow2[1]);
            *(float2*)(ob + (size_t)r0 * Dm + c) = w0;
            *(float2*)(ob + (size_t)(r0 + 8) * Dm + c) = w1;
        }
    }
}

// ---------------------------------------------------------------------------
// Launch
// ---------------------------------------------------------------------------
extern "C" void kernel_launch(void* const* d_in, const int* in_sizes, int n_in,
                              void* d_out, int out_size)
{
    const float* x      = (const float*)d_in[0];  // [B,S,D]
    const float* w_attn = (const float*)d_in[1];  // [D,3D]
    const float* b_attn = (const float*)d_in[2];  // [3D]
    const float* w_proj = (const float*)d_in[3];  // [D,D]
    const float* b_proj = (const float*)d_in[4];  // [D]
    float* out = (float*)d_out;

    float *qkv, *attn, *xc, *wat, *wpt;
    cudaGetSymbolAddress((void**)&qkv,  g_qkv);
    cudaGetSymbolAddress((void**)&attn, g_attn);
    cudaGetSymbolAddress((void**)&xc,   g_xc);
    cudaGetSymbolAddress((void**)&wat,  g_wat);
    cudaGetSymbolAddress((void**)&wpt,  g_wpt);

    // Allow 96KB dynamic smem for the GEMM (idempotent, non-captured call)
    const int GEMM_SMEM = 6 * (int)GSTAGE;   // 98304
    cudaFuncSetAttribute(gemm_mma_tf32,
                         cudaFuncAttributeMaxDynamicSharedMemorySize, GEMM_SMEM);

    // 0) tf32 rounding / weight transposes
    cvt_tf32_kernel<<<(Mrows * Dm) / (4 * 256), 256>>>(x, xc);
    transpose_cvt_kernel<<<dim3(QKVCOLS / 32, Dm / 32), dim3(32, 8)>>>(
        w_attn, wat, Dm, QKVCOLS);
    transpose_cvt_kernel<<<dim3(Dm / 32, Dm / 32), dim3(32, 8)>>>(
        w_proj, wpt, Dm, Dm);

    // 1) QKV projection (mma.sync tf32, k-stage 32, 96KB smem pipeline)
    gemm_mma_tf32<<<dim3(QKVCOLS / 128, Mrows / 128), 256, GEMM_SMEM>>>(
        xc, wat, b_attn, qkv, Mrows, QKVCOLS, Dm);

    // 2) Causal multi-head attention (mma.sync tf32 flash + ldmatrix)
    attn_mma_kernel<<<dim3(Sq / 128, Hn, Bsz), 256>>>(qkv, attn);

    // 3) Output projection
    gemm_mma_tf32<<<dim3(Dm / 128, Mrows / 128), 256, GEMM_SMEM>>>(
        attn, wpt, b_proj, out, Mrows, Dm, Dm);
}